// round 17
// baseline (speedup 1.0000x reference)
#include <cuda_runtime.h>

// EquivariantLayerNorm: dim=1184 = 256(l=0) + 384(l=1) + 320(l=2) + 224(l=3)
// float4 chunk k holds vec indices [32k, 32k+32):
//   k=0,1 -> g0 | k=2,3,4 -> g1 | k=5,6 -> g2 | k=7 -> g2 (lane<16)/g3 | k=8,9 -> g3
// Structural index facts (deterministic _build_indices for these IRREPS):
//   scalar_indices = [0..255];  irrep_idx(f) = f                    (f < 256)
//                               = 256 + (f-256)/3                   (256 <= f < 640)
//                               = 384 + (f-640)/5                   (640 <= f < 960)
//                               = 448 + (f-960)/7                   (960 <= f < 1184)
// Key: 4 consecutive features within one group span at most 2 irreps (q, q+1),
// so each float4 needs only 2 weight gathers + 1 const-division.
#define DIM   1184
#define VECS  296
#define EPSV  1e-5f
#define WPB   8      // warps per block (256 threads) — measured optimum (128/256/512 swept)

template <int BASE_F, int BASE_I, int D>
__device__ __forceinline__ float4 scale_chunk(float4 v, float rg,
                                              const float* __restrict__ weight,
                                              int vi) {
    const int t = vi * 4 - BASE_F;
    const unsigned q = (unsigned)t / (unsigned)D;        // const division -> mul-hi
    const int r = t - (int)q * D;
    const float wlo = __ldg(weight + BASE_I + q);
    unsigned hi = BASE_I + q + 1u;
    if (hi > 479u) hi = 479u;                            // clamp (value unused when clamped)
    const float whi = __ldg(weight + hi);
    float4 o;
    o.x = v.x * rg * ((r + 0 < D) ? wlo : whi);
    o.y = v.y * rg * ((r + 1 < D) ? wlo : whi);
    o.z = v.z * rg * ((r + 2 < D) ? wlo : whi);
    o.w = v.w * rg * ((r + 3 < D) ? wlo : whi);
    return o;
}

template <bool GUARD>
__global__ __launch_bounds__(32 * WPB)
void eln_kernel(const float4* __restrict__ x, float4* __restrict__ out,
                const float* __restrict__ weight,
                const float* __restrict__ bias, int n_rows) {
    const int lane = threadIdx.x & 31;
    const int warp = threadIdx.x >> 5;
    const int row  = blockIdx.x * WPB + warp;
    if (GUARD && row >= n_rows) return;

    const float4* __restrict__ xr  = x   + (size_t)row * VECS;
    float4*       __restrict__ orw = out + (size_t)row * VECS;

    // ---- front-batched coalesced streaming loads: whole row in registers ----
    float4 v[10];
    #pragma unroll
    for (int k = 0; k < 9; k++) v[k] = __ldcs(xr + lane + 32 * k);
    const bool has9 = (lane < 8);
    v[9] = make_float4(0.f, 0.f, 0.f, 0.f);
    if (has9) v[9] = __ldcs(xr + lane + 288);

    // ---- per-lane stats, compile-time group routing ----
    float ssum = 0.f, q0 = 0.f, q1 = 0.f, q2 = 0.f, q3 = 0.f;
    #pragma unroll
    for (int k = 0; k < 10; k++) {
        float d = fmaf(v[k].x, v[k].x, fmaf(v[k].y, v[k].y,
                  fmaf(v[k].z, v[k].z, v[k].w * v[k].w)));
        if (k < 2)       { ssum += v[k].x + v[k].y + v[k].z + v[k].w; q0 += d; }
        else if (k < 5)  q1 += d;
        else if (k < 7)  q2 += d;
        else if (k == 7) { if (lane < 16) q2 += d; else q3 += d; }
        else             q3 += d;
    }

    const float4* __restrict__ w4 = (const float4*)weight;  // identity map for f<256
    const float4* __restrict__ b4 = (const float4*)bias;

    // ---- stage 1: reduce scalar-group stats only, store chunks 0-1 early ----
    #pragma unroll
    for (int o = 16; o; o >>= 1) {
        ssum += __shfl_xor_sync(0xffffffffu, ssum, o);
        q0   += __shfl_xor_sync(0xffffffffu, q0,   o);
    }
    const float m  = ssum * (1.0f / 256.0f);
    const float r0 = rsqrtf(q0 * (1.0f / 256.0f) - m * m + EPSV);

    #pragma unroll
    for (int k = 0; k < 2; k++) {
        const int vi = lane + 32 * k;
        float4 w = __ldg(w4 + vi), b = __ldg(b4 + vi), o;
        o.x = fmaf((v[k].x - m) * r0, w.x, b.x);
        o.y = fmaf((v[k].y - m) * r0, w.y, b.y);
        o.z = fmaf((v[k].z - m) * r0, w.z, b.z);
        o.w = fmaf((v[k].w - m) * r0, w.w, b.w);
        __stcs(orw + vi, o);
    }

    // ---- stage 2: reduce remaining group stats, store chunks 2-9 ----
    #pragma unroll
    for (int o = 16; o; o >>= 1) {
        q1 += __shfl_xor_sync(0xffffffffu, q1, o);
        q2 += __shfl_xor_sync(0xffffffffu, q2, o);
        q3 += __shfl_xor_sync(0xffffffffu, q3, o);
    }
    const float r1 = rsqrtf(q1 * (1.0f / 384.0f) + EPSV);
    const float r2 = rsqrtf(q2 * (1.0f / 320.0f) + EPSV);
    const float r3 = rsqrtf(q3 * (1.0f / 224.0f) + EPSV);

    // chunks 2-4: g1 (d=3)
    #pragma unroll
    for (int k = 2; k < 5; k++) {
        const int vi = lane + 32 * k;
        __stcs(orw + vi, scale_chunk<256, 256, 3>(v[k], r1, weight, vi));
    }
    // chunks 5-6: g2 (d=5)
    #pragma unroll
    for (int k = 5; k < 7; k++) {
        const int vi = lane + 32 * k;
        __stcs(orw + vi, scale_chunk<640, 384, 5>(v[k], r2, weight, vi));
    }
    // chunk 7: g2 (lane<16) / g3 (lane>=16)
    {
        const int vi = lane + 32 * 7;
        float4 o;
        if (lane < 16) o = scale_chunk<640, 384, 5>(v[7], r2, weight, vi);
        else           o = scale_chunk<960, 448, 7>(v[7], r3, weight, vi);
        __stcs(orw + vi, o);
    }
    // chunk 8: g3 (d=7)
    {
        const int vi = lane + 32 * 8;
        __stcs(orw + vi, scale_chunk<960, 448, 7>(v[8], r3, weight, vi));
    }
    // chunk 9: g3, lanes < 8 only
    if (has9) {
        const int vi = lane + 32 * 9;
        __stcs(orw + vi, scale_chunk<960, 448, 7>(v[9], r3, weight, vi));
    }
}

extern "C" void kernel_launch(void* const* d_in, const int* in_sizes, int n_in,
                              void* d_out, int out_size) {
    const float* x      = (const float*)d_in[0];
    const float* weight = (const float*)d_in[1];
    const float* bias   = (const float*)d_in[2];
    // d_in[3..6] = group_idx / irrep_idx / scalar_indices / scalar_group
    //   (structure compile-time known; see header comment)
    float* out = (float*)d_out;

    const int n_rows = in_sizes[0] / DIM;

    if ((n_rows % WPB) == 0) {
        eln_kernel<false><<<n_rows / WPB, 32 * WPB>>>((const float4*)x, (float4*)out,
                                                      weight, bias, n_rows);
    } else {
        eln_kernel<true><<<(n_rows + WPB - 1) / WPB, 32 * WPB>>>((const float4*)x, (float4*)out,
                                                                 weight, bias, n_rows);
    }
}